// round 13
// baseline (speedup 1.0000x reference)
#include <cuda_runtime.h>
#include <cuda_bf16.h>

#define B_  16
#define S_  2048
#define D_  128
#define BQ  64
#define BK  64
#define NT  128
#define NTILES (S_/BK)

#define QSTR 528             // Q/K smem row stride bytes (128 f32 + 16 pad)
#define VSTR 272             // V^T smem row stride bytes (64 f32 + 16 pad)

#define OFF_Q   0            // 64 x 528 = 33792
#define OFF_K   33792        // 64 x 528 = 33792
#define OFF_VT  67584        // 128 x 272 = 34816
#define OFF_KPM 102400       // 64 B
#define SMEM_BYTES (102400 + 128)

__device__ __forceinline__ unsigned smem_u32(const void* p) {
    unsigned a;
    asm("{ .reg .u64 t; cvta.to.shared.u64 t, %1; cvt.u32.u64 %0, t; }" : "=r"(a) : "l"(p));
    return a;
}

#define LDSM_X4(r0,r1,r2,r3,a) \
    asm("ldmatrix.sync.aligned.m8n8.x4.shared.b16 {%0,%1,%2,%3}, [%4];" \
        : "=r"(r0),"=r"(r1),"=r"(r2),"=r"(r3) : "r"(a) : "memory")

// tf32 m16n8k8: A = 4 regs, B = 2 regs, C = 4 f32
#define MMAT(c,a0,a1,a2,a3,b0,b1) \
    asm("mma.sync.aligned.m16n8k8.row.col.f32.tf32.tf32.f32 " \
        "{%0,%1,%2,%3}, {%4,%5,%6,%7}, {%8,%9}, {%0,%1,%2,%3};" \
        : "+f"((c)[0]),"+f"((c)[1]),"+f"((c)[2]),"+f"((c)[3]) \
        : "r"(a0),"r"(a1),"r"(a2),"r"(a3),"r"(b0),"r"(b1))

#define F2TF(u, f) asm("cvt.rna.tf32.f32 %0, %1;" : "=r"(u) : "f"(f))

// cooperative load of [ROWS][128] f32 tile -> tf32-rounded smem (stride SSTR)
template<int ROWS, int SSTR>
__device__ __forceinline__ void load_tf32(char* smc, const float* g, int off, float mul) {
    const float4* g4 = reinterpret_cast<const float4*>(g);
    #pragma unroll
    for (int it = 0; it < (ROWS * 32) / NT; ++it) {
        int idx = threadIdx.x + it * NT;
        int r = idx >> 5, c4 = idx & 31;
        float4 v = g4[idx];
        unsigned w0, w1, w2, w3;
        F2TF(w0, v.x * mul); F2TF(w1, v.y * mul);
        F2TF(w2, v.z * mul); F2TF(w3, v.w * mul);
        *reinterpret_cast<uint4*>(smc + off + r * SSTR + c4 * 16) = make_uint4(w0, w1, w2, w3);
    }
}

// transposed V load: smem V^T[dcol][key] tf32. global reads coalesced over dcol.
__device__ __forceinline__ void load_vT(char* smc, const float* g) {
    #pragma unroll
    for (int it = 0; it < (128 * 16) / NT; ++it) {
        int idx = threadIdx.x + it * NT;
        int c  = idx & 127;        // dcol
        int r4 = idx >> 7;         // key group of 4
        unsigned w0, w1, w2, w3;
        F2TF(w0, g[(size_t)(r4*4+0)*D_ + c]);
        F2TF(w1, g[(size_t)(r4*4+1)*D_ + c]);
        F2TF(w2, g[(size_t)(r4*4+2)*D_ + c]);
        F2TF(w3, g[(size_t)(r4*4+3)*D_ + c]);
        *reinterpret_cast<uint4*>(smc + OFF_VT + c * VSTR + r4 * 16) = make_uint4(w0, w1, w2, w3);
    }
}

__global__ __launch_bounds__(NT, 2)
void fa_tf32_kernel(const float* __restrict__ Q, const float* __restrict__ K,
                    const float* __restrict__ V, const unsigned char* __restrict__ kpm,
                    const int* __restrict__ cls, float* __restrict__ O)
{
    extern __shared__ char smc[];
    const unsigned sb = smem_u32(smc);
    const int tid  = threadIdx.x;
    const int wid  = tid >> 5;       // 0..3
    const int lane = tid & 31;
    const int b  = blockIdx.y;
    const int q0 = blockIdx.x * BQ;

    const int i0 = cls[b*3 + 0];
    const int i1 = cls[b*3 + 1];
    const int i2 = cls[b*3 + 2];

    const int rg0 = q0 + wid*16 + (lane >> 2);
    const int rg1 = rg0 + 8;
    const bool isr1_0 = (rg0 == i1), isr2_0 = (rg0 == i2);
    const bool isr1_1 = (rg1 == i1), isr2_1 = (rg1 == i2);

    // Q tile -> smem (tf32-rounded, pre-scaled by 1/sqrt(d))
    load_tf32<BQ, QSTR>(smc, Q + ((size_t)b*S_ + q0)*D_, OFF_Q, 0.08838834764831845f);

    float o[16][4];
    #pragma unroll
    for (int i = 0; i < 16; ++i)
        #pragma unroll
        for (int j = 0; j < 4; ++j) o[i][j] = 0.0f;
    float lsum0 = 0.0f, lsum1 = 0.0f;

    // ldmatrix lane base addresses (byte offsets)
    const unsigned qbase = (unsigned)((wid*16 + (lane&7) + ((lane>>3)&1)*8) * QSTR + ((lane>>4)*4)*4);
    const unsigned kbase = (unsigned)(((lane&7) + (lane>>4)*8) * QSTR + (((lane>>3)&1)*4)*4);
    const unsigned vbase = (unsigned)(((lane&7) + (lane>>4)*8) * VSTR + (((lane>>3)&1)*4)*4);

    const int m_ = lane & 3;
    const unsigned src0 = (unsigned)((lane & 28) | (m_ >> 1));
    const unsigned src2 = src0 | 2u;
    const bool modd = (m_ & 1) != 0;

    for (int tl = 0; tl < NTILES; ++tl) {
        const int kb = tl * BK;
        __syncthreads();   // previous tile's K/V readers done

        load_tf32<BK, QSTR>(smc, K + ((size_t)b*S_ + kb)*D_, OFF_K, 1.0f);
        load_vT(smc, V + ((size_t)b*S_ + kb)*D_);
        if (tid < 16) ((unsigned*)(smc + OFF_KPM))[tid] = ((const unsigned*)(kpm + (size_t)b*S_ + kb))[tid];
        __syncthreads();

        // ---- QK^T : 16 rows x 64 keys, single-pass tf32 (16 k-steps of 8) ----
        float s[8][4];
        #pragma unroll
        for (int i = 0; i < 8; ++i)
            #pragma unroll
            for (int j = 0; j < 4; ++j) s[i][j] = 0.0f;

        #pragma unroll
        for (int ks = 0; ks < 16; ++ks) {
            unsigned a0, a1, a2, a3;
            LDSM_X4(a0, a1, a2, a3, sb + OFF_Q + qbase + (unsigned)(ks*32));
            #pragma unroll
            for (int np2 = 0; np2 < 4; ++np2) {   // two 8-key n-tiles per x4
                unsigned b0, b1, b2, b3;
                LDSM_X4(b0, b1, b2, b3, sb + OFF_K + (unsigned)(np2*16*QSTR) + kbase + (unsigned)(ks*32));
                MMAT(s[2*np2],   a0, a1, a2, a3, b0, b1);
                MMAT(s[2*np2+1], a0, a1, a2, a3, b2, b3);
            }
        }

        // ---- mask + exp (in place, f32) ----
        const unsigned char* kpms = (const unsigned char*)(smc + OFF_KPM);
        #pragma unroll
        for (int nt = 0; nt < 8; ++nt) {
            const int jl0 = nt*8 + m_*2;
            const int jg0 = kb + jl0, jg1 = jg0 + 1;
            const bool kp0 = kpms[jl0] != 0, kp1 = kpms[jl0 + 1] != 0;
            const bool key1_0 = ((jg0 > i1) && (jg0 <= i2)) || (jg0 == 0);
            const bool key1_1 = ((jg1 > i1) && (jg1 <= i2)) || (jg1 == 0);
            const bool key2_0 = ((jg0 > i0) && (jg0 <= i1)) || (jg0 == 0);
            const bool key2_1 = ((jg1 > i0) && (jg1 <= i1)) || (jg1 == 0);

            float v0 = (kp0 || (isr1_0 && key1_0) || (isr2_0 && key2_0)) ? -1e30f : s[nt][0];
            float v1 = (kp1 || (isr1_0 && key1_1) || (isr2_0 && key2_1)) ? -1e30f : s[nt][1];
            float v2 = (kp0 || (isr1_1 && key1_0) || (isr2_1 && key2_0)) ? -1e30f : s[nt][2];
            float v3 = (kp1 || (isr1_1 && key1_1) || (isr2_1 && key2_1)) ? -1e30f : s[nt][3];

            float p0 = __expf(fminf(v0, 60.0f));
            float p1 = __expf(fminf(v1, 60.0f));
            float p2 = __expf(fminf(v2, 60.0f));
            float p3 = __expf(fminf(v3, 60.0f));
            lsum0 += p0 + p1;
            lsum1 += p2 + p3;
            s[nt][0] = p0; s[nt][1] = p1; s[nt][2] = p2; s[nt][3] = p3;
        }

        // ---- P·V : 8 k-steps (one per score n-tile), a-frag via shfl ----
        #pragma unroll
        for (int ks = 0; ks < 8; ++ks) {
            unsigned u0, u1, u2, u3;
            F2TF(u0, s[ks][0]); F2TF(u1, s[ks][1]);
            F2TF(u2, s[ks][2]); F2TF(u3, s[ks][3]);
            unsigned t00 = __shfl_sync(0xffffffffu, u0, src0);
            unsigned t01 = __shfl_sync(0xffffffffu, u1, src0);
            unsigned t20 = __shfl_sync(0xffffffffu, u2, src0);
            unsigned t21 = __shfl_sync(0xffffffffu, u3, src0);
            unsigned t02 = __shfl_sync(0xffffffffu, u0, src2);
            unsigned t03 = __shfl_sync(0xffffffffu, u1, src2);
            unsigned t22 = __shfl_sync(0xffffffffu, u2, src2);
            unsigned t23 = __shfl_sync(0xffffffffu, u3, src2);
            unsigned a0 = modd ? t01 : t00;
            unsigned a1 = modd ? t21 : t20;
            unsigned a2 = modd ? t03 : t02;
            unsigned a3 = modd ? t23 : t22;

            #pragma unroll
            for (int dp2 = 0; dp2 < 8; ++dp2) {   // two 8-dcol n-tiles per x4
                unsigned v0, v1, v2, v3;
                LDSM_X4(v0, v1, v2, v3, sb + OFF_VT + (unsigned)(dp2*16*VSTR) + vbase + (unsigned)(ks*32));
                MMAT(o[2*dp2],   a0, a1, a2, a3, v0, v1);
                MMAT(o[2*dp2+1], a0, a1, a2, a3, v2, v3);
            }
        }
    }

    // ---- final: reduce l across quad, normalize, store ----
    lsum0 += __shfl_xor_sync(0xffffffffu, lsum0, 1);
    lsum0 += __shfl_xor_sync(0xffffffffu, lsum0, 2);
    lsum1 += __shfl_xor_sync(0xffffffffu, lsum1, 1);
    lsum1 += __shfl_xor_sync(0xffffffffu, lsum1, 2);
    const float inv0 = 1.0f / lsum0;
    const float inv1 = 1.0f / lsum1;

    float* O0 = O + ((size_t)b*S_ + rg0)*D_;
    float* O1 = O + ((size_t)b*S_ + rg1)*D_;
    #pragma unroll
    for (int dt = 0; dt < 16; ++dt) {
        const int col = dt*8 + m_*2;
        float2 w0 = make_float2(o[dt][0]*inv0, o[dt][1]*inv0);
        float2 w1 = make_float2(o[dt][2]*inv1, o[dt][3]*inv1);
        *reinterpret_cast<float2*>(O0 + col) = w0;
        *reinterpret_cast<float2*>(O1 + col) = w1;
    }
}

extern "C" void kernel_launch(void* const* d_in, const int* in_sizes, int n_in,
                              void* d_out, int out_size)
{
    const float* Q = (const float*)d_in[0];
    const float* K = (const float*)d_in[1];
    const float* V = (const float*)d_in[2];
    const unsigned char* kpm = (const unsigned char*)d_in[3];
    const int* cls = (const int*)d_in[4];
    float* O = (float*)d_out;

    cudaFuncSetAttribute(fa_tf32_kernel, cudaFuncAttributeMaxDynamicSharedMemorySize, SMEM_BYTES);
    dim3 grid(S_/BQ, B_);
    fa_tf32_kernel<<<grid, NT, SMEM_BYTES>>>(Q, K, V, kpm, cls, O);
}

// round 14
// speedup vs baseline: 2.0799x; 2.0799x over previous
#include <cuda_runtime.h>
#include <cuda_fp16.h>

#define B_  16
#define S_  2048
#define D_  128
#define BQ  128
#define BK  64
#define NT  256
#define NTILES (S_/BK)

#define STR 272              // smem row stride in bytes (128 f16 + 8 pad)

#define OFF_Q   0            // 128 x 272 = 34816
#define OFF_K   34816        // 64 x 272  = 17408
#define OFF_V   52224        // 64 x 272  = 17408
#define OFF_KPM 69632
#define SMEM_BYTES (69632 + 128)

__device__ __forceinline__ unsigned smem_u32(const void* p) {
    unsigned a;
    asm("{ .reg .u64 t; cvta.to.shared.u64 t, %1; cvt.u32.u64 %0, t; }" : "=r"(a) : "l"(p));
    return a;
}

// Non-volatile (schedulable). "memory" clobber keeps ordering vs stores/barriers.
#define LDSM_X4(r0,r1,r2,r3,a) \
    asm("ldmatrix.sync.aligned.m8n8.x4.shared.b16 {%0,%1,%2,%3}, [%4];" \
        : "=r"(r0),"=r"(r1),"=r"(r2),"=r"(r3) : "r"(a) : "memory")
#define LDSM_X4T(r0,r1,r2,r3,a) \
    asm("ldmatrix.sync.aligned.m8n8.x4.trans.shared.b16 {%0,%1,%2,%3}, [%4];" \
        : "=r"(r0),"=r"(r1),"=r"(r2),"=r"(r3) : "r"(a) : "memory")

#define MMA(c,a0,a1,a2,a3,b0,b1) \
    asm("mma.sync.aligned.m16n8k16.row.col.f32.f16.f16.f32 " \
        "{%0,%1,%2,%3}, {%4,%5,%6,%7}, {%8,%9}, {%0,%1,%2,%3};" \
        : "+f"((c)[0]),"+f"((c)[1]),"+f"((c)[2]),"+f"((c)[3]) \
        : "r"(a0),"r"(a1),"r"(a2),"r"(a3),"r"(b0),"r"(b1))

__device__ __forceinline__ unsigned pack2h(float x, float y) {
    __half2 h = __floats2half2_rn(x, y);   // x -> low half
    return *reinterpret_cast<unsigned*>(&h);
}

// cooperative load of [ROWS][128] f32 tile -> f16 smem (stride 272B)
template<int ROWS>
__device__ __forceinline__ void load_f16(char* smc, const float* g, int off, float mul) {
    const float4* g4 = reinterpret_cast<const float4*>(g);
    #pragma unroll
    for (int it = 0; it < (ROWS * 32) / NT; ++it) {
        int idx = threadIdx.x + it * NT;
        int r = idx >> 5, c4 = idx & 31;
        float4 v = g4[idx];
        unsigned h0 = pack2h(v.x * mul, v.y * mul);
        unsigned h1 = pack2h(v.z * mul, v.w * mul);
        *reinterpret_cast<uint2*>(smc + off + r * STR + c4 * 8) = make_uint2(h0, h1);
    }
}

__global__ __launch_bounds__(NT, 1)
void fa_f16_kernel(const float* __restrict__ Q, const float* __restrict__ K,
                   const float* __restrict__ V, const unsigned char* __restrict__ kpm,
                   const int* __restrict__ cls, float* __restrict__ O)
{
    extern __shared__ char smc[];
    const unsigned sb = smem_u32(smc);
    const int tid  = threadIdx.x;
    const int wid  = tid >> 5;
    const int lane = tid & 31;
    const int b  = blockIdx.y;
    const int q0 = blockIdx.x * BQ;

    const int i0 = cls[b*3 + 0];
    const int i1 = cls[b*3 + 1];
    const int i2 = cls[b*3 + 2];

    // this thread's two q-rows (within warp's 16-row block)
    const int rg0 = q0 + wid*16 + (lane >> 2);
    const int rg1 = rg0 + 8;
    const bool isr1_0 = (rg0 == i1), isr2_0 = (rg0 == i2);
    const bool isr1_1 = (rg1 == i1), isr2_1 = (rg1 == i2);

    // Q tile -> smem f16, pre-scaled by 1/sqrt(d)
    load_f16<BQ>(smc, Q + ((size_t)b*S_ + q0)*D_, OFF_Q, 0.08838834764831845f);

    float o[16][4];
    #pragma unroll
    for (int i = 0; i < 16; ++i)
        #pragma unroll
        for (int j = 0; j < 4; ++j) o[i][j] = 0.0f;
    float lsum0 = 0.0f, lsum1 = 0.0f;

    // per-warp ldmatrix lane addressing (byte offsets within a tile)
    const unsigned qrow_off = (unsigned)((wid*16 + (lane & 15)) * STR) + ((lane >> 4) ? 16u : 0u);
    const unsigned krow     = (unsigned)((((lane >> 4) & 1) * 8 + (lane & 7)) * STR) + (((lane >> 3) & 1) ? 16u : 0u);
    const unsigned vrow     = (unsigned)(((((lane >> 3) & 1) * 8) + (lane & 7)) * STR) + ((lane >> 4) ? 16u : 0u);

    const int m_ = lane & 3;

    for (int tl = 0; tl < NTILES; ++tl) {
        const int kb = tl * BK;
        __syncthreads();   // previous tile's smem readers done

        load_f16<BK>(smc, K + ((size_t)b*S_ + kb)*D_, OFF_K, 1.0f);
        load_f16<BK>(smc, V + ((size_t)b*S_ + kb)*D_, OFF_V, 1.0f);
        if (tid < 16) ((unsigned*)(smc + OFF_KPM))[tid] = ((const unsigned*)(kpm + (size_t)b*S_ + kb))[tid];
        __syncthreads();

        // ---- QK^T : scores s[8 n-tiles][4], single-pass f16 ----
        float s[8][4];
        #pragma unroll
        for (int i = 0; i < 8; ++i)
            #pragma unroll
            for (int j = 0; j < 4; ++j) s[i][j] = 0.0f;

        #pragma unroll
        for (int ks = 0; ks < 8; ++ks) {           // k over D in steps of 16
            const unsigned kbyte = (unsigned)(ks * 32);   // 16 f16
            unsigned aq[4];
            LDSM_X4(aq[0], aq[1], aq[2], aq[3], sb + OFF_Q + qrow_off + kbyte);
            #pragma unroll
            for (int np = 0; np < 4; ++np) {       // n-tile pairs: keys np*16
                unsigned roff = (unsigned)(np * 16 * STR) + krow + kbyte;
                unsigned b0, b1, b2, b3;
                LDSM_X4(b0, b1, b2, b3, sb + OFF_K + roff);
                MMA(s[2*np],   aq[0], aq[1], aq[2], aq[3], b0, b1);
                MMA(s[2*np+1], aq[0], aq[1], aq[2], aq[3], b2, b3);
            }
        }

        // ---- mask + exp + pack into P fragments (registers only) ----
        unsigned ph[8][2];
        const unsigned char* kpms = (const unsigned char*)(smc + OFF_KPM);
        #pragma unroll
        for (int nt = 0; nt < 8; ++nt) {
            const int jl0 = nt*8 + m_*2;
            const int jg0 = kb + jl0, jg1 = jg0 + 1;
            const bool kp0 = kpms[jl0] != 0, kp1 = kpms[jl0 + 1] != 0;
            const bool key1_0 = ((jg0 > i1) && (jg0 <= i2)) || (jg0 == 0);
            const bool key1_1 = ((jg1 > i1) && (jg1 <= i2)) || (jg1 == 0);
            const bool key2_0 = ((jg0 > i0) && (jg0 <= i1)) || (jg0 == 0);
            const bool key2_1 = ((jg1 > i0) && (jg1 <= i1)) || (jg1 == 0);

            float v0 = (kp0 || (isr1_0 && key1_0) || (isr2_0 && key2_0)) ? -1e30f : s[nt][0];
            float v1 = (kp1 || (isr1_0 && key1_1) || (isr2_0 && key2_1)) ? -1e30f : s[nt][1];
            float v2 = (kp0 || (isr1_1 && key1_0) || (isr2_1 && key2_0)) ? -1e30f : s[nt][2];
            float v3 = (kp1 || (isr1_1 && key1_1) || (isr2_1 && key2_1)) ? -1e30f : s[nt][3];

            float p0 = __expf(v0);
            float p1 = __expf(v1);
            float p2 = __expf(v2);
            float p3 = __expf(v3);
            lsum0 += p0 + p1;
            lsum1 += p2 + p3;
            ph[nt][0] = pack2h(p0, p1);
            ph[nt][1] = pack2h(p2, p3);
        }

        // ---- P·V : O += P * V, C-frag -> A-frag direct (no shfl) ----
        #pragma unroll
        for (int ks = 0; ks < 4; ++ks) {           // keys in steps of 16
            const unsigned krow_off = (unsigned)(ks * 16 * STR) + vrow;
            const unsigned a0 = ph[2*ks][0], a1 = ph[2*ks][1];
            const unsigned a2 = ph[2*ks+1][0], a3 = ph[2*ks+1][1];
            #pragma unroll
            for (int dp = 0; dp < 8; ++dp) {       // dcol pairs: dcol dp*16
                unsigned off = krow_off + (unsigned)(dp * 32);
                unsigned v0, v1, v2, v3;
                LDSM_X4T(v0, v1, v2, v3, sb + OFF_V + off);
                MMA(o[2*dp],   a0, a1, a2, a3, v0, v1);
                MMA(o[2*dp+1], a0, a1, a2, a3, v2, v3);
            }
        }
    }

    // ---- final: reduce l across quad, normalize, store ----
    lsum0 += __shfl_xor_sync(0xffffffffu, lsum0, 1);
    lsum0 += __shfl_xor_sync(0xffffffffu, lsum0, 2);
    lsum1 += __shfl_xor_sync(0xffffffffu, lsum1, 1);
    lsum1 += __shfl_xor_sync(0xffffffffu, lsum1, 2);
    const float inv0 = 1.0f / lsum0;
    const float inv1 = 1.0f / lsum1;

    float* O0 = O + ((size_t)b*S_ + rg0)*D_;
    float* O1 = O + ((size_t)b*S_ + rg1)*D_;
    #pragma unroll
    for (int nt = 0; nt < 16; ++nt) {
        const int col = nt*8 + m_*2;
        float2 w0 = make_float2(o[nt][0]*inv0, o[nt][1]*inv0);
        float2 w1 = make_float2(o[nt][2]*inv1, o[nt][3]*inv1);
        *reinterpret_cast<float2*>(O0 + col) = w0;
        *reinterpret_cast<float2*>(O1 + col) = w1;
    }
}

extern "C" void kernel_launch(void* const* d_in, const int* in_sizes, int n_in,
                              void* d_out, int out_size)
{
    const float* Q = (const float*)d_in[0];
    const float* K = (const float*)d_in[1];
    const float* V = (const float*)d_in[2];
    const unsigned char* kpm = (const unsigned char*)d_in[3];
    const int* cls = (const int*)d_in[4];
    float* O = (float*)d_out;

    cudaFuncSetAttribute(fa_f16_kernel, cudaFuncAttributeMaxDynamicSharedMemorySize, SMEM_BYTES);
    dim3 grid(S_/BQ, B_);
    fa_f16_kernel<<<grid, NT, SMEM_BYTES>>>(Q, K, V, kpm, cls, O);
}

// round 15
// speedup vs baseline: 2.1653x; 1.0411x over previous
#include <cuda_runtime.h>
#include <cuda_fp16.h>

#define B_  16
#define S_  2048
#define D_  128
#define BQ  128
#define BK  64
#define NT  256
#define NTILES (S_/BK)

#define STR 272              // smem row stride in bytes (128 f16 + 8 pad)

#define OFF_Q   0            // 128 x 272 = 34816
#define OFF_K   34816        // 64 x 272  = 17408
#define OFF_V   52224        // 64 x 272  = 17408
#define OFF_KPM 69632
#define SMEM_BYTES (69632 + 128)

__device__ __forceinline__ unsigned smem_u32(const void* p) {
    unsigned a;
    asm("{ .reg .u64 t; cvta.to.shared.u64 t, %1; cvt.u32.u64 %0, t; }" : "=r"(a) : "l"(p));
    return a;
}

// Non-volatile (schedulable). "memory" clobber keeps ordering vs stores/barriers.
#define LDSM_X4(r0,r1,r2,r3,a) \
    asm("ldmatrix.sync.aligned.m8n8.x4.shared.b16 {%0,%1,%2,%3}, [%4];" \
        : "=r"(r0),"=r"(r1),"=r"(r2),"=r"(r3) : "r"(a) : "memory")
#define LDSM_X4T(r0,r1,r2,r3,a) \
    asm("ldmatrix.sync.aligned.m8n8.x4.trans.shared.b16 {%0,%1,%2,%3}, [%4];" \
        : "=r"(r0),"=r"(r1),"=r"(r2),"=r"(r3) : "r"(a) : "memory")

#define MMA(c,a0,a1,a2,a3,b0,b1) \
    asm("mma.sync.aligned.m16n8k16.row.col.f32.f16.f16.f32 " \
        "{%0,%1,%2,%3}, {%4,%5,%6,%7}, {%8,%9}, {%0,%1,%2,%3};" \
        : "+f"((c)[0]),"+f"((c)[1]),"+f"((c)[2]),"+f"((c)[3]) \
        : "r"(a0),"r"(a1),"r"(a2),"r"(a3),"r"(b0),"r"(b1))

__device__ __forceinline__ unsigned pack2h(float x, float y) {
    __half2 h = __floats2half2_rn(x, y);   // x -> low half
    return *reinterpret_cast<unsigned*>(&h);
}

// cooperative load of [ROWS][128] f32 tile -> f16 smem (stride 272B)
template<int ROWS>
__device__ __forceinline__ void load_f16(char* smc, const float* g, int off, float mul) {
    const float4* g4 = reinterpret_cast<const float4*>(g);
    #pragma unroll
    for (int it = 0; it < (ROWS * 32) / NT; ++it) {
        int idx = threadIdx.x + it * NT;
        int r = idx >> 5, c4 = idx & 31;
        float4 v = g4[idx];
        unsigned h0 = pack2h(v.x * mul, v.y * mul);
        unsigned h1 = pack2h(v.z * mul, v.w * mul);
        *reinterpret_cast<uint2*>(smc + off + r * STR + c4 * 8) = make_uint2(h0, h1);
    }
}

__global__ __launch_bounds__(NT, 1)
void fa_f16_kernel(const float* __restrict__ Q, const float* __restrict__ K,
                   const float* __restrict__ V, const unsigned char* __restrict__ kpm,
                   const int* __restrict__ cls, float* __restrict__ O)
{
    extern __shared__ char smc[];
    const unsigned sb = smem_u32(smc);
    const int tid  = threadIdx.x;
    const int wid  = tid >> 5;
    const int lane = tid & 31;
    const int b  = blockIdx.y;
    const int q0 = blockIdx.x * BQ;

    const int i0 = cls[b*3 + 0];
    const int i1 = cls[b*3 + 1];
    const int i2 = cls[b*3 + 2];

    // this thread's two q-rows (within warp's 16-row block)
    const int rg0 = q0 + wid*16 + (lane >> 2);
    const int rg1 = rg0 + 8;
    const bool isr1_0 = (rg0 == i1), isr2_0 = (rg0 == i2);
    const bool isr1_1 = (rg1 == i1), isr2_1 = (rg1 == i2);
    const bool special = isr1_0 || isr2_0 || isr1_1 || isr2_1;

    // Q tile -> smem f16, pre-scaled by 1/sqrt(d)
    load_f16<BQ>(smc, Q + ((size_t)b*S_ + q0)*D_, OFF_Q, 0.08838834764831845f);

    // per-warp ldmatrix lane addressing (byte offsets within a tile)
    const unsigned qrow_off = (unsigned)((wid*16 + (lane & 15)) * STR) + ((lane >> 4) ? 16u : 0u);
    const unsigned krow     = (unsigned)((((lane >> 4) & 1) * 8 + (lane & 7)) * STR) + (((lane >> 3) & 1) ? 16u : 0u);
    const unsigned vrow     = (unsigned)(((((lane >> 3) & 1) * 8) + (lane & 7)) * STR) + ((lane >> 4) ? 16u : 0u);

    __syncthreads();          // Q smem complete
    // ---- Q fragments resident in registers for all tiles ----
    unsigned aq[8][4];
    #pragma unroll
    for (int ks = 0; ks < 8; ++ks)
        LDSM_X4(aq[ks][0], aq[ks][1], aq[ks][2], aq[ks][3],
                sb + OFF_Q + qrow_off + (unsigned)(ks * 32));

    float o[16][4];
    #pragma unroll
    for (int i = 0; i < 16; ++i)
        #pragma unroll
        for (int j = 0; j < 4; ++j) o[i][j] = 0.0f;
    float lsum0 = 0.0f, lsum1 = 0.0f;

    const int m_ = lane & 3;

    for (int tl = 0; tl < NTILES; ++tl) {
        const int kb = tl * BK;
        __syncthreads();   // previous tile's smem readers done

        load_f16<BK>(smc, K + ((size_t)b*S_ + kb)*D_, OFF_K, 1.0f);
        load_f16<BK>(smc, V + ((size_t)b*S_ + kb)*D_, OFF_V, 1.0f);
        if (tid < 16) ((unsigned*)(smc + OFF_KPM))[tid] = ((const unsigned*)(kpm + (size_t)b*S_ + kb))[tid];
        __syncthreads();

        // ---- QK^T : scores s[8 n-tiles][4], single-pass f16, Q from regs ----
        float s[8][4];
        #pragma unroll
        for (int i = 0; i < 8; ++i)
            #pragma unroll
            for (int j = 0; j < 4; ++j) s[i][j] = 0.0f;

        #pragma unroll
        for (int ks = 0; ks < 8; ++ks) {           // k over D in steps of 16
            const unsigned kbyte = (unsigned)(ks * 32);
            #pragma unroll
            for (int np = 0; np < 4; ++np) {       // n-tile pairs: keys np*16
                unsigned roff = (unsigned)(np * 16 * STR) + krow + kbyte;
                unsigned b0, b1, b2, b3;
                LDSM_X4(b0, b1, b2, b3, sb + OFF_K + roff);
                MMA(s[2*np],   aq[ks][0], aq[ks][1], aq[ks][2], aq[ks][3], b0, b1);
                MMA(s[2*np+1], aq[ks][0], aq[ks][1], aq[ks][2], aq[ks][3], b2, b3);
            }
        }

        // ---- mask (fast path for non-special threads) ----
        const unsigned short* kpmh = (const unsigned short*)(smc + OFF_KPM);
        if (!special) {
            #pragma unroll
            for (int nt = 0; nt < 8; ++nt) {
                unsigned kpw = kpmh[nt*4 + m_];
                if (kpw & 0xFFu)  { s[nt][0] = -1e30f; s[nt][2] = -1e30f; }
                if (kpw >> 8)     { s[nt][1] = -1e30f; s[nt][3] = -1e30f; }
            }
        } else {
            #pragma unroll
            for (int nt = 0; nt < 8; ++nt) {
                unsigned kpw = kpmh[nt*4 + m_];
                const int jl0 = nt*8 + m_*2;
                const int jg0 = kb + jl0, jg1 = jg0 + 1;
                const bool kp0 = (kpw & 0xFFu) != 0, kp1 = (kpw >> 8) != 0;
                const bool key1_0 = ((jg0 > i1) && (jg0 <= i2)) || (jg0 == 0);
                const bool key1_1 = ((jg1 > i1) && (jg1 <= i2)) || (jg1 == 0);
                const bool key2_0 = ((jg0 > i0) && (jg0 <= i1)) || (jg0 == 0);
                const bool key2_1 = ((jg1 > i0) && (jg1 <= i1)) || (jg1 == 0);
                if (kp0 || (isr1_0 && key1_0) || (isr2_0 && key2_0)) s[nt][0] = -1e30f;
                if (kp1 || (isr1_0 && key1_1) || (isr2_0 && key2_1)) s[nt][1] = -1e30f;
                if (kp0 || (isr1_1 && key1_0) || (isr2_1 && key2_0)) s[nt][2] = -1e30f;
                if (kp1 || (isr1_1 && key1_1) || (isr2_1 && key2_1)) s[nt][3] = -1e30f;
            }
        }

        // ---- exp + pack into P fragments (registers only) ----
        unsigned ph[8][2];
        #pragma unroll
        for (int nt = 0; nt < 8; ++nt) {
            float p0 = __expf(s[nt][0]);
            float p1 = __expf(s[nt][1]);
            float p2 = __expf(s[nt][2]);
            float p3 = __expf(s[nt][3]);
            lsum0 += p0 + p1;
            lsum1 += p2 + p3;
            ph[nt][0] = pack2h(p0, p1);
            ph[nt][1] = pack2h(p2, p3);
        }

        // ---- P·V : O += P * V, C-frag -> A-frag direct (no shfl) ----
        #pragma unroll
        for (int ks = 0; ks < 4; ++ks) {           // keys in steps of 16
            const unsigned krow_off = (unsigned)(ks * 16 * STR) + vrow;
            const unsigned a0 = ph[2*ks][0], a1 = ph[2*ks][1];
            const unsigned a2 = ph[2*ks+1][0], a3 = ph[2*ks+1][1];
            #pragma unroll
            for (int dp = 0; dp < 8; ++dp) {       // dcol pairs: dcol dp*16
                unsigned off = krow_off + (unsigned)(dp * 32);
                unsigned v0, v1, v2, v3;
                LDSM_X4T(v0, v1, v2, v3, sb + OFF_V + off);
                MMA(o[2*dp],   a0, a1, a2, a3, v0, v1);
                MMA(o[2*dp+1], a0, a1, a2, a3, v2, v3);
            }
        }
    }

    // ---- final: reduce l across quad, normalize, store ----
    lsum0 += __shfl_xor_sync(0xffffffffu, lsum0, 1);
    lsum0 += __shfl_xor_sync(0xffffffffu, lsum0, 2);
    lsum1 += __shfl_xor_sync(0xffffffffu, lsum1, 1);
    lsum1 += __shfl_xor_sync(0xffffffffu, lsum1, 2);
    const float inv0 = 1.0f / lsum0;
    const float inv1 = 1.0f / lsum1;

    float* O0 = O + ((size_t)b*S_ + rg0)*D_;
    float* O1 = O + ((size_t)b*S_ + rg1)*D_;
    #pragma unroll
    for (int nt = 0; nt < 16; ++nt) {
        const int col = nt*8 + m_*2;
        float2 w0 = make_float2(o[nt][0]*inv0, o[nt][1]*inv0);
        float2 w1 = make_float2(o[nt][2]*inv1, o[nt][3]*inv1);
        *reinterpret_cast<float2*>(O0 + col) = w0;
        *reinterpret_cast<float2*>(O1 + col) = w1;
    }
}

extern "C" void kernel_launch(void* const* d_in, const int* in_sizes, int n_in,
                              void* d_out, int out_size)
{
    const float* Q = (const float*)d_in[0];
    const float* K = (const float*)d_in[1];
    const float* V = (const float*)d_in[2];
    const unsigned char* kpm = (const unsigned char*)d_in[3];
    const int* cls = (const int*)d_in[4];
    float* O = (float*)d_out;

    cudaFuncSetAttribute(fa_f16_kernel, cudaFuncAttributeMaxDynamicSharedMemorySize, SMEM_BYTES);
    dim3 grid(S_/BQ, B_);
    fa_f16_kernel<<<grid, NT, SMEM_BYTES>>>(Q, K, V, kpm, cls, O);
}

// round 16
// speedup vs baseline: 2.2086x; 1.0200x over previous
#include <cuda_runtime.h>
#include <cuda_fp16.h>

#define B_  16
#define S_  2048
#define D_  128
#define BQ  128
#define BK  64
#define NT  256
#define NTILES (S_/BK)

#define STR 272              // smem row stride in bytes (128 f16 + 8 pad)

#define OFF_Q   0            // 128 x 272 = 34816
#define OFF_K0  34816        // 64 x 272  = 17408
#define OFF_K1  52224
#define OFF_V0  69632
#define OFF_V1  87040
#define OFF_KPM 104448       // 2 x 64B slots
#define SMEM_BYTES (104576 + 128)

// f16 scratch (written by cvt prepass, read by main kernel)
__device__ __half g_Qh[B_*S_*D_];
__device__ __half g_Kh[B_*S_*D_];
__device__ __half g_Vh[B_*S_*D_];

__device__ __forceinline__ unsigned smem_u32(const void* p) {
    unsigned a;
    asm("{ .reg .u64 t; cvta.to.shared.u64 t, %1; cvt.u32.u64 %0, t; }" : "=r"(a) : "l"(p));
    return a;
}

#define LDSM_X4(r0,r1,r2,r3,a) \
    asm("ldmatrix.sync.aligned.m8n8.x4.shared.b16 {%0,%1,%2,%3}, [%4];" \
        : "=r"(r0),"=r"(r1),"=r"(r2),"=r"(r3) : "r"(a) : "memory")
#define LDSM_X4T(r0,r1,r2,r3,a) \
    asm("ldmatrix.sync.aligned.m8n8.x4.trans.shared.b16 {%0,%1,%2,%3}, [%4];" \
        : "=r"(r0),"=r"(r1),"=r"(r2),"=r"(r3) : "r"(a) : "memory")

#define MMA(c,a0,a1,a2,a3,b0,b1) \
    asm("mma.sync.aligned.m16n8k16.row.col.f32.f16.f16.f32 " \
        "{%0,%1,%2,%3}, {%4,%5,%6,%7}, {%8,%9}, {%0,%1,%2,%3};" \
        : "+f"((c)[0]),"+f"((c)[1]),"+f"((c)[2]),"+f"((c)[3]) \
        : "r"(a0),"r"(a1),"r"(a2),"r"(a3),"r"(b0),"r"(b1))

#define CPA16(dst, src) \
    asm volatile("cp.async.cg.shared.global [%0], [%1], 16;" :: "r"(dst), "l"(src))
#define CPA4(dst, src) \
    asm volatile("cp.async.ca.shared.global [%0], [%1], 4;" :: "r"(dst), "l"(src))
#define CP_COMMIT()  asm volatile("cp.async.commit_group;")
#define CP_WAIT(n)   asm volatile("cp.async.wait_group %0;" :: "n"(n) : "memory")

__device__ __forceinline__ unsigned pack2h(float x, float y) {
    __half2 h = __floats2half2_rn(x, y);   // x -> low half
    return *reinterpret_cast<unsigned*>(&h);
}

// ---- prepass: f32 -> f16 conversion (Q pre-scaled) ----
__global__ __launch_bounds__(256, 8)
void cvt_kernel(const float* __restrict__ Q, const float* __restrict__ K,
                const float* __restrict__ V)
{
    const int t = blockIdx.x * 256 + threadIdx.x;   // one float4 per thread
    const float* src;
    __half* dst;
    float mul = 1.0f;
    if (blockIdx.y == 0)      { src = Q; dst = g_Qh; mul = 0.08838834764831845f; }
    else if (blockIdx.y == 1) { src = K; dst = g_Kh; }
    else                      { src = V; dst = g_Vh; }
    float4 v = reinterpret_cast<const float4*>(src)[t];
    unsigned h0 = pack2h(v.x * mul, v.y * mul);
    unsigned h1 = pack2h(v.z * mul, v.w * mul);
    reinterpret_cast<uint2*>(dst)[t] = make_uint2(h0, h1);
}

// prefetch f16 K/V tile + kpm into smem buffers via cp.async (one group)
__device__ __forceinline__ void prefetch_kv(unsigned sb, const __half* kh, const __half* vh,
                                            const unsigned char* kpmg, unsigned offK,
                                            unsigned offV, int slot, int tid)
{
    const char* gk = (const char*)kh;
    const char* gv = (const char*)vh;
    #pragma unroll
    for (int it = 0; it < 4; ++it) {
        int idx = tid + it * NT;              // 16B chunk over [64 rows][16 chunks]
        unsigned r = (unsigned)(idx >> 4), c = (unsigned)(idx & 15);
        CPA16(sb + offK + r * STR + c * 16, gk + idx * 16);
        CPA16(sb + offV + r * STR + c * 16, gv + idx * 16);
    }
    if (tid < 16) CPA4(sb + OFF_KPM + (unsigned)(slot * 64 + tid * 4), kpmg + tid * 4);
    CP_COMMIT();
}

__global__ __launch_bounds__(NT, 1)
void fa_f16_kernel(const unsigned char* __restrict__ kpm,
                   const int* __restrict__ cls, float* __restrict__ O)
{
    extern __shared__ char smc[];
    const unsigned sb = smem_u32(smc);
    const int tid  = threadIdx.x;
    const int wid  = tid >> 5;
    const int lane = tid & 31;
    const int b  = blockIdx.y;
    const int q0 = blockIdx.x * BQ;

    const int i0 = cls[b*3 + 0];
    const int i1 = cls[b*3 + 1];
    const int i2 = cls[b*3 + 2];

    const int rg0 = q0 + wid*16 + (lane >> 2);
    const int rg1 = rg0 + 8;
    const bool isr1_0 = (rg0 == i1), isr2_0 = (rg0 == i2);
    const bool isr1_1 = (rg1 == i1), isr2_1 = (rg1 == i2);
    const bool special = isr1_0 || isr2_0 || isr1_1 || isr2_1;

    // prologue: prefetch tile 0 K/V (f16) into buffer 0
    prefetch_kv(sb, g_Kh + (size_t)b*S_*D_, g_Vh + (size_t)b*S_*D_,
                kpm + (size_t)b*S_, OFF_K0, OFF_V0, 0, tid);

    // Q tile (already scaled f16) -> smem
    {
        const uint4* qg = reinterpret_cast<const uint4*>(g_Qh + ((size_t)b*S_ + q0)*D_);
        #pragma unroll
        for (int it = 0; it < 8; ++it) {
            int idx = tid + it * NT;          // 16B chunk over [128 rows][16 chunks]
            unsigned r = (unsigned)(idx >> 4), c = (unsigned)(idx & 15);
            *reinterpret_cast<uint4*>(smc + OFF_Q + r * STR + c * 16) = qg[idx];
        }
    }

    // ldmatrix lane addressing
    const unsigned qrow_off = (unsigned)((wid*16 + (lane & 15)) * STR) + ((lane >> 4) ? 16u : 0u);
    const unsigned krow     = (unsigned)((((lane >> 4) & 1) * 8 + (lane & 7)) * STR) + (((lane >> 3) & 1) ? 16u : 0u);
    const unsigned vrow     = (unsigned)(((((lane >> 3) & 1) * 8) + (lane & 7)) * STR) + ((lane >> 4) ? 16u : 0u);

    __syncthreads();          // Q smem complete
    unsigned aq[8][4];
    #pragma unroll
    for (int ks = 0; ks < 8; ++ks)
        LDSM_X4(aq[ks][0], aq[ks][1], aq[ks][2], aq[ks][3],
                sb + OFF_Q + qrow_off + (unsigned)(ks * 32));

    float o[16][4];
    #pragma unroll
    for (int i = 0; i < 16; ++i)
        #pragma unroll
        for (int j = 0; j < 4; ++j) o[i][j] = 0.0f;
    float lsum0 = 0.0f, lsum1 = 0.0f;

    const int m_ = lane & 3;

    for (int tl = 0; tl < NTILES; ++tl) {
        const int kb = tl * BK;
        const int p  = tl & 1;
        const unsigned offK = p ? OFF_K1 : OFF_K0;
        const unsigned offV = p ? OFF_V1 : OFF_V0;

        // issue next tile's prefetch into the other buffer, then wait for this tile
        if (tl + 1 < NTILES) {
            prefetch_kv(sb, g_Kh + ((size_t)b*S_ + kb + BK)*D_,
                        g_Vh + ((size_t)b*S_ + kb + BK)*D_,
                        kpm + (size_t)b*S_ + kb + BK,
                        p ? OFF_K0 : OFF_K1, p ? OFF_V0 : OFF_V1, 1 - p, tid);
            CP_WAIT(1);
        } else {
            CP_WAIT(0);
        }
        __syncthreads();      // this tile's copies visible to all warps

        // ---- QK^T : single-pass f16, Q from regs ----
        float s[8][4];
        #pragma unroll
        for (int i = 0; i < 8; ++i)
            #pragma unroll
            for (int j = 0; j < 4; ++j) s[i][j] = 0.0f;

        #pragma unroll
        for (int ks = 0; ks < 8; ++ks) {
            const unsigned kbyte = (unsigned)(ks * 32);
            #pragma unroll
            for (int np = 0; np < 4; ++np) {
                unsigned roff = (unsigned)(np * 16 * STR) + krow + kbyte;
                unsigned b0, b1, b2, b3;
                LDSM_X4(b0, b1, b2, b3, sb + offK + roff);
                MMA(s[2*np],   aq[ks][0], aq[ks][1], aq[ks][2], aq[ks][3], b0, b1);
                MMA(s[2*np+1], aq[ks][0], aq[ks][1], aq[ks][2], aq[ks][3], b2, b3);
            }
        }

        // ---- mask (fast path for non-special threads) ----
        const unsigned short* kpmh = (const unsigned short*)(smc + OFF_KPM + p*64);
        if (!special) {
            #pragma unroll
            for (int nt = 0; nt < 8; ++nt) {
                unsigned kpw = kpmh[nt*4 + m_];
                if (kpw & 0xFFu)  { s[nt][0] = -1e30f; s[nt][2] = -1e30f; }
                if (kpw >> 8)     { s[nt][1] = -1e30f; s[nt][3] = -1e30f; }
            }
        } else {
            #pragma unroll
            for (int nt = 0; nt < 8; ++nt) {
                unsigned kpw = kpmh[nt*4 + m_];
                const int jl0 = nt*8 + m_*2;
                const int jg0 = kb + jl0, jg1 = jg0 + 1;
                const bool kp0 = (kpw & 0xFFu) != 0, kp1 = (kpw >> 8) != 0;
                const bool key1_0 = ((jg0 > i1) && (jg0 <= i2)) || (jg0 == 0);
                const bool key1_1 = ((jg1 > i1) && (jg1 <= i2)) || (jg1 == 0);
                const bool key2_0 = ((jg0 > i0) && (jg0 <= i1)) || (jg0 == 0);
                const bool key2_1 = ((jg1 > i0) && (jg1 <= i1)) || (jg1 == 0);
                if (kp0 || (isr1_0 && key1_0) || (isr2_0 && key2_0)) s[nt][0] = -1e30f;
                if (kp1 || (isr1_0 && key1_1) || (isr2_0 && key2_1)) s[nt][1] = -1e30f;
                if (kp0 || (isr1_1 && key1_0) || (isr2_1 && key2_0)) s[nt][2] = -1e30f;
                if (kp1 || (isr1_1 && key1_1) || (isr2_1 && key2_1)) s[nt][3] = -1e30f;
            }
        }

        // ---- exp + pack into P fragments ----
        unsigned ph[8][2];
        #pragma unroll
        for (int nt = 0; nt < 8; ++nt) {
            float p0 = __expf(s[nt][0]);
            float p1 = __expf(s[nt][1]);
            float p2 = __expf(s[nt][2]);
            float p3 = __expf(s[nt][3]);
            lsum0 += p0 + p1;
            lsum1 += p2 + p3;
            ph[nt][0] = pack2h(p0, p1);
            ph[nt][1] = pack2h(p2, p3);
        }

        // ---- P·V : C-frag -> A-frag direct ----
        #pragma unroll
        for (int ks = 0; ks < 4; ++ks) {
            const unsigned krow_off = (unsigned)(ks * 16 * STR) + vrow;
            const unsigned a0 = ph[2*ks][0], a1 = ph[2*ks][1];
            const unsigned a2 = ph[2*ks+1][0], a3 = ph[2*ks+1][1];
            #pragma unroll
            for (int dp = 0; dp < 8; ++dp) {
                unsigned off = krow_off + (unsigned)(dp * 32);
                unsigned v0, v1, v2, v3;
                LDSM_X4T(v0, v1, v2, v3, sb + offV + off);
                MMA(o[2*dp],   a0, a1, a2, a3, v0, v1);
                MMA(o[2*dp+1], a0, a1, a2, a3, v2, v3);
            }
        }

        __syncthreads();      // buf p readers done; next iter prefetch may overwrite
    }

    // ---- final: reduce l across quad, normalize, store ----
    lsum0 += __shfl_xor_sync(0xffffffffu, lsum0, 1);
    lsum0 += __shfl_xor_sync(0xffffffffu, lsum0, 2);
    lsum1 += __shfl_xor_sync(0xffffffffu, lsum1, 1);
    lsum1 += __shfl_xor_sync(0xffffffffu, lsum1, 2);
    const float inv0 = 1.0f / lsum0;
    const float inv1 = 1.0f / lsum1;

    float* O0 = O + ((size_t)b*S_ + rg0)*D_;
    float* O1 = O + ((size_t)b*S_ + rg1)*D_;
    #pragma unroll
    for (int nt = 0; nt < 16; ++nt) {
        const int col = nt*8 + m_*2;
        float2 w0 = make_float2(o[nt][0]*inv0, o[nt][1]*inv0);
        float2 w1 = make_float2(o[nt][2]*inv1, o[nt][3]*inv1);
        *reinterpret_cast<float2*>(O0 + col) = w0;
        *reinterpret_cast<float2*>(O1 + col) = w1;
    }
}

extern "C" void kernel_launch(void* const* d_in, const int* in_sizes, int n_in,
                              void* d_out, int out_size)
{
    const float* Q = (const float*)d_in[0];
    const float* K = (const float*)d_in[1];
    const float* V = (const float*)d_in[2];
    const unsigned char* kpm = (const unsigned char*)d_in[3];
    const int* cls = (const int*)d_in[4];
    float* O = (float*)d_out;

    // prepass: f32 -> f16 (Q pre-scaled)
    dim3 cgrid((B_*S_*D_/4) / 256, 3);
    cvt_kernel<<<cgrid, 256>>>(Q, K, V);

    cudaFuncSetAttribute(fa_f16_kernel, cudaFuncAttributeMaxDynamicSharedMemorySize, SMEM_BYTES);
    dim3 grid(S_/BQ, B_);
    fa_f16_kernel<<<grid, NT, SMEM_BYTES>>>(kpm, cls, O);
}